// round 14
// baseline (speedup 1.0000x reference)
#include <cuda_runtime.h>
#include <cuda_bf16.h>
#include <cuda_fp16.h>
#include <math.h>
#include <stdint.h>

// ---------------------------------------------------------------------------
// GCN 2-layer forward. R14: GEMM1 software-pipelined — W1 smem-resident,
// A tile double-buffered via register staging, 1 sync/chunk. (R13 profile:
// DRAM-stream-bound at 2.75TB/s, tensor 27%.)
// ---------------------------------------------------------------------------

#define NMAX 100000
#define EMAX 1600000
#define FIN  512
#define HID  128
#define NCLS 40
#define NBLK ((NMAX + 1023) / 1024)

typedef unsigned long long ull;

// --------------------------- device scratch --------------------------------
__device__ int   g_is64;
__device__ int   g_cnt[NMAX];
__device__ int   g_off[NMAX + 1];
__device__ int   g_cur[NMAX];
__device__ float g_dis[NMAX];
__device__ int   g_blksum[NBLK];
__device__ int   g_blkoff[NBLK];
__device__ int   g_esrc[EMAX];
__device__ float g_enrm[EMAX];
__device__ __align__(128) __half g_w1h[(size_t)HID * FIN];          // W1^T fp16
__device__ __align__(128) __half g_w2t[(size_t)NCLS * HID];         // W2^T fp16
__device__ __align__(128) __half2 g_h1f[(size_t)NMAX * (HID / 2)];  // x@W1
__device__ __align__(128) __half2 g_a1f[(size_t)NMAX * (HID / 2)];  // relu(agg)
__device__ __align__(128) __half2 g_h2f[(size_t)NMAX * (NCLS / 2)]; // a1@W2

// --------------------------- helpers ---------------------------------------
__device__ __forceinline__ int load_idx(const int* __restrict__ p, long long slot, int is64) {
    return is64 ? p[2 * slot] : p[slot];
}
__global__ void k_probe(const unsigned* __restrict__ p) {
    unsigned nz = 0;
    for (int i = 1; i < 256; i += 2) nz |= p[i];
    g_is64 = (nz == 0u) ? 1 : 0;
}
__device__ __forceinline__ unsigned pack_h2(float x, float y) {
    __half hx = __float2half_rn(x), hy = __float2half_rn(y);
    return (unsigned)__half_as_ushort(hx) | ((unsigned)__half_as_ushort(hy) << 16);
}
__device__ __forceinline__ float2 u32_as_f2h(unsigned u) {
    __half2 h = *reinterpret_cast<__half2*>(&u);
    return __half22float2(h);
}

#define MMA_F16(c, a, b0, b1)                                                    \
    asm volatile("mma.sync.aligned.m16n8k16.row.col.f32.f16.f16.f32 "            \
        "{%0,%1,%2,%3}, {%4,%5,%6,%7}, {%8,%9}, {%0,%1,%2,%3};"                  \
        : "+f"((c)[0]), "+f"((c)[1]), "+f"((c)[2]), "+f"((c)[3])                 \
        : "r"((a)[0]), "r"((a)[1]), "r"((a)[2]), "r"((a)[3]), "r"(b0), "r"(b1))

// --------------------------- CSR construction ------------------------------
__global__ void k_init(int n) {
    int i = blockIdx.x * blockDim.x + threadIdx.x;
    if (i < n) { g_cnt[i] = 0; g_cur[i] = 0; }
}
__global__ void k_hist(const int* __restrict__ ei, int E) {
    int e = blockIdx.x * blockDim.x + threadIdx.x;
    int is64 = g_is64;
    if (e < E) atomicAdd(&g_cnt[load_idx(ei, (long long)E + e, is64)], 1);
}
__global__ void k_scanA(int n) {
    __shared__ int sh[1024];
    int t = threadIdx.x;
    int i = blockIdx.x * 1024 + t;
    sh[t] = (i < n) ? g_cnt[i] : 0;
    __syncthreads();
#pragma unroll
    for (int d = 512; d > 0; d >>= 1) {
        if (t < d) sh[t] += sh[t + d];
        __syncthreads();
    }
    if (t == 0) g_blksum[blockIdx.x] = sh[0];
}
__global__ void k_scanB(int nb) {
    __shared__ int sh[128];
    int t = threadIdx.x;
    int v = (t < nb) ? g_blksum[t] : 0;
    sh[t] = v;
    __syncthreads();
#pragma unroll
    for (int d = 1; d < 128; d <<= 1) {
        int u = 0;
        if (t >= d) u = sh[t - d];
        __syncthreads();
        if (t >= d) sh[t] += u;
        __syncthreads();
    }
    if (t < nb) g_blkoff[t] = sh[t] - v;
}
__global__ void k_scanC(int n) {
    __shared__ int sh[1024];
    int t = threadIdx.x;
    int i = blockIdx.x * 1024 + t;
    int c = (i < n) ? g_cnt[i] : 0;
    sh[t] = c;
    __syncthreads();
#pragma unroll
    for (int d = 1; d < 1024; d <<= 1) {
        int u = 0;
        if (t >= d) u = sh[t - d];
        __syncthreads();
        if (t >= d) sh[t] += u;
        __syncthreads();
    }
    if (i < n) {
        int off = g_blkoff[blockIdx.x] + sh[t] - c;
        g_off[i] = off;
        g_dis[i] = rsqrtf((float)(c + 1));
        if (i == n - 1) g_off[n] = off + c;
    }
}
__global__ void k_scatter(const int* __restrict__ ei, int E) {
    int e = blockIdx.x * blockDim.x + threadIdx.x;
    int is64 = g_is64;
    if (e < E) {
        int s = load_idx(ei, e, is64);
        int d = load_idx(ei, (long long)E + e, is64);
        int p = g_off[d] + atomicAdd(&g_cur[d], 1);
        g_esrc[p] = s;
        g_enrm[p] = g_dis[s] * g_dis[d];
    }
}

// --------------- weight conversions (fp32 -> fp16, transposed) --------------
__global__ void k_wconv(const float* __restrict__ W1) {
    int i = blockIdx.x * blockDim.x + threadIdx.x;
    if (i < FIN * HID) {
        int k = i / HID, n = i % HID;
        g_w1h[(size_t)n * FIN + k] = __float2half_rn(W1[i]);
    }
}
__global__ void k_wconv2(const float* __restrict__ W2) {
    int i = blockIdx.x * blockDim.x + threadIdx.x;
    if (i < HID * NCLS) {
        int k = i / NCLS, n = i % NCLS;
        g_w2t[(size_t)n * HID + k] = __float2half_rn(W2[i]);
    }
}

// ---------- GEMM1 via mma.sync fp16 (pipelined): [N,512]x[512,128] ---------
// CTA tile 128x128. W1 fully smem-resident (stride 520 halves: 260 words,
// 260%32=4 -> fragment banks 4*lg + lk/2, all-distinct). A double-buffered:
// LDG next chunk into regs before MMAs, convert+STS after, 1 sync/chunk
// (write buffer was last read in iter ch-1, protected by its trailing sync).
#define SA  40    // A smem stride in halves
#define SBR 520   // B resident stride in halves
#define G1_SMEM ((128 * SBR + 2 * 128 * SA) * 2)   // 153,600 B

__global__ __launch_bounds__(256, 1) void k_gemm1_mma(const float* __restrict__ X, int M) {
    extern __shared__ __half smem[];
    __half* sB  = smem;                    // 128 x 520
    __half* sA0 = smem + 128 * SBR;        // 128 x 40
    __half* sA1 = sA0 + 128 * SA;          // 128 x 40

    int t    = threadIdx.x;
    int lane = t & 31;
    int wid  = t >> 5;
    int wm   = wid & 3;
    int wn   = wid >> 2;
    int blockRow = blockIdx.x * 128;

    // Preload whole B: 128 n-rows x 512 halves (128 ull per row)
    for (int i = t; i < 128 * (FIN / 4); i += 256) {
        int n = i >> 7;          // /128
        int q = i & 127;
        *(ull*)&sB[n * SBR + q * 4] = *(const ull*)&g_w1h[(size_t)n * FIN + q * 4];
    }

    float acc[2][8][4];
#pragma unroll
    for (int mi = 0; mi < 2; mi++)
#pragma unroll
        for (int ni = 0; ni < 8; ni++)
#pragma unroll
            for (int c = 0; c < 4; c++) acc[mi][ni][c] = 0.f;

    const int lg = lane >> 2;
    const int lk = (lane & 3) * 2;

    // this thread's A-fill slots: f = t + i*256 -> row r=f>>3, k-offset c4=f&7
    int rowA[4], colA[4];
    const float* gA[4];
#pragma unroll
    for (int i = 0; i < 4; i++) {
        int f = t + i * 256;
        rowA[i] = f >> 3;
        colA[i] = (f & 7) * 4;
        int gr = blockRow + rowA[i];
        if (gr >= M) gr = M - 1;
        gA[i] = &X[(size_t)gr * FIN + colA[i]];
    }

    // prologue: load chunk 0, convert, store to sA0
    float4 va[4];
#pragma unroll
    for (int i = 0; i < 4; i++) va[i] = *(const float4*)gA[i];
#pragma unroll
    for (int i = 0; i < 4; i++) {
        ull h = (ull)pack_h2(va[i].x, va[i].y) | ((ull)pack_h2(va[i].z, va[i].w) << 32);
        *(ull*)&sA0[rowA[i] * SA + colA[i]] = h;
    }
    __syncthreads();   // covers B preload + sA0

    for (int ch = 0; ch < 16; ch++) {
        // prefetch next A chunk into registers (overlaps with MMAs below)
        if (ch < 15) {
#pragma unroll
            for (int i = 0; i < 4; i++)
                va[i] = *(const float4*)(gA[i] + (ch + 1) * 32);
        }

        const __half* sAc = (ch & 1) ? sA1 : sA0;
        int kt = ch * 32;
#pragma unroll
        for (int kk = 0; kk < 2; kk++) {
            int k0 = kk * 16 + lk;
            uint32_t ah[2][4];
#pragma unroll
            for (int mi = 0; mi < 2; mi++) {
                int r0 = wm * 32 + mi * 16 + lg;
                ah[mi][0] = *(const uint32_t*)&sAc[r0 * SA + k0];
                ah[mi][1] = *(const uint32_t*)&sAc[(r0 + 8) * SA + k0];
                ah[mi][2] = *(const uint32_t*)&sAc[r0 * SA + k0 + 8];
                ah[mi][3] = *(const uint32_t*)&sAc[(r0 + 8) * SA + k0 + 8];
            }
            int kb = kt + kk * 16 + lk;
#pragma unroll
            for (int ni = 0; ni < 8; ni++) {
                int c0 = wn * 64 + ni * 8 + lg;
                uint32_t b0 = *(const uint32_t*)&sB[c0 * SBR + kb];
                uint32_t b1 = *(const uint32_t*)&sB[c0 * SBR + kb + 8];
#pragma unroll
                for (int mi = 0; mi < 2; mi++)
                    MMA_F16(acc[mi][ni], ah[mi], b0, b1);
            }
        }

        if (ch < 15) {
            __half* sAn = (ch & 1) ? sA0 : sA1;
#pragma unroll
            for (int i = 0; i < 4; i++) {
                ull h = (ull)pack_h2(va[i].x, va[i].y) | ((ull)pack_h2(va[i].z, va[i].w) << 32);
                *(ull*)&sAn[rowA[i] * SA + colA[i]] = h;
            }
            __syncthreads();
        }
    }

#pragma unroll
    for (int mi = 0; mi < 2; mi++) {
        int r0 = blockRow + wm * 32 + mi * 16 + (lane >> 2);
#pragma unroll
        for (int ni = 0; ni < 8; ni++) {
            int c2 = (wn * 64 + ni * 8 + (lane & 3) * 2) >> 1;
            if (r0 < M)
                g_h1f[(size_t)r0 * (HID / 2) + c2] = __floats2half2_rn(acc[mi][ni][0], acc[mi][ni][1]);
            if (r0 + 8 < M)
                g_h1f[(size_t)(r0 + 8) * (HID / 2) + c2] = __floats2half2_rn(acc[mi][ni][2], acc[mi][ni][3]);
        }
    }
}

// ------------- Aggregation 1: warp per node, fp16 gather, fp16 out ---------
__global__ void k_agg1(const float* __restrict__ b1, int n) {
    int w = (blockIdx.x * blockDim.x + threadIdx.x) >> 5;
    if (w >= n) return;
    int l = threadIdx.x & 31;

    float di = g_dis[w];
    float dself = di * di;

    const __half2* self = &g_h1f[(size_t)w * (HID / 2) + l * 2];
    float2 s0 = __half22float2(self[0]);
    float2 s1 = __half22float2(self[1]);
    float4 acc = make_float4(s0.x * dself, s0.y * dself, s1.x * dself, s1.y * dself);

    int beg = g_off[w], end = g_off[w + 1];
    for (int p = beg; p < end; p++) {
        int   s  = g_esrc[p];
        float wt = g_enrm[p];
        uint2 v = *(const uint2*)&g_h1f[(size_t)s * (HID / 2) + l * 2];
        float2 f0 = u32_as_f2h(v.x);
        float2 f1 = u32_as_f2h(v.y);
        acc.x = fmaf(f0.x, wt, acc.x);
        acc.y = fmaf(f0.y, wt, acc.y);
        acc.z = fmaf(f1.x, wt, acc.z);
        acc.w = fmaf(f1.y, wt, acc.w);
    }
    float4 bb = *(const float4*)&b1[l * 4];
    acc.x = fmaxf(acc.x + bb.x, 0.f);
    acc.y = fmaxf(acc.y + bb.y, 0.f);
    acc.z = fmaxf(acc.z + bb.z, 0.f);
    acc.w = fmaxf(acc.w + bb.w, 0.f);
    uint2 o;
    o.x = pack_h2(acc.x, acc.y);
    o.y = pack_h2(acc.z, acc.w);
    *(uint2*)&g_a1f[(size_t)w * (HID / 2) + l * 2] = o;
}

// ---------- GEMM2 via mma.sync fp16: [N,128] x [128,40] -> g_h2f ----------
#define SB2 136

__global__ __launch_bounds__(256) void k_gemm2_mma(int M) {
    __shared__ __half sA[128 * SA];
    __shared__ __half sB[NCLS * SB2];

    int t    = threadIdx.x;
    int lane = t & 31;
    int wid  = t >> 5;
    int blockRow = blockIdx.x * 128;

    float acc[5][4];
#pragma unroll
    for (int ni = 0; ni < 5; ni++)
#pragma unroll
        for (int c = 0; c < 4; c++) acc[ni][c] = 0.f;

    for (int i = t; i < NCLS * (HID / 4); i += 256) {
        int n = i / (HID / 4);
        int q = i % (HID / 4);
        *(ull*)&sB[n * SB2 + q * 4] = *(const ull*)&g_w2t[(size_t)n * HID + q * 4];
    }

    const int lg = lane >> 2;
    const int lk = (lane & 3) * 2;
    const __half* a1 = (const __half*)g_a1f;

    for (int ch = 0; ch < 4; ch++) {
        int kt = ch * 32;
#pragma unroll
        for (int i = 0; i < 4; i++) {
            int f  = t + i * 256;
            int r  = f >> 3;
            int c4 = f & 7;
            int gr = blockRow + r;
            if (gr >= M) gr = M - 1;
            *(ull*)&sA[r * SA + c4 * 4] = *(const ull*)&a1[(size_t)gr * HID + kt + c4 * 4];
        }
        __syncthreads();

#pragma unroll
        for (int kk = 0; kk < 2; kk++) {
            int k0 = kk * 16 + lk;
            int r0 = wid * 16 + lg;
            uint32_t a[4];
            a[0] = *(const uint32_t*)&sA[r0 * SA + k0];
            a[1] = *(const uint32_t*)&sA[(r0 + 8) * SA + k0];
            a[2] = *(const uint32_t*)&sA[r0 * SA + k0 + 8];
            a[3] = *(const uint32_t*)&sA[(r0 + 8) * SA + k0 + 8];
            int kb = kt + kk * 16 + lk;
#pragma unroll
            for (int ni = 0; ni < 5; ni++) {
                int c0 = ni * 8 + lg;
                uint32_t b0 = *(const uint32_t*)&sB[c0 * SB2 + kb];
                uint32_t b1 = *(const uint32_t*)&sB[c0 * SB2 + kb + 8];
                MMA_F16(acc[ni], a, b0, b1);
            }
        }
        __syncthreads();
    }

    int r0 = blockRow + wid * 16 + (lane >> 2);
#pragma unroll
    for (int ni = 0; ni < 5; ni++) {
        int c2 = (ni * 8 + (lane & 3) * 2) >> 1;
        if (r0 < M)
            g_h2f[(size_t)r0 * (NCLS / 2) + c2] = __floats2half2_rn(acc[ni][0], acc[ni][1]);
        if (r0 + 8 < M)
            g_h2f[(size_t)(r0 + 8) * (NCLS / 2) + c2] = __floats2half2_rn(acc[ni][2], acc[ni][3]);
    }
}

// ------- Aggregation 2 + bias + log_softmax: warp per node, fp16 gather ----
__global__ void k_agg2(const float* __restrict__ b2, float* __restrict__ out, int n) {
    int w = (blockIdx.x * blockDim.x + threadIdx.x) >> 5;
    if (w >= n) return;
    int l = threadIdx.x & 31;
    bool act = (l < NCLS / 2);

    float di = g_dis[w];
    float dself = di * di;

    float2 acc = make_float2(0.f, 0.f);
    if (act) {
        float2 f = __half22float2(g_h2f[(size_t)w * (NCLS / 2) + l]);
        acc.x = f.x * dself;
        acc.y = f.y * dself;
    }

    int beg = g_off[w], end = g_off[w + 1];
    for (int p = beg; p < end; p++) {
        int   s  = g_esrc[p];
        float wt = g_enrm[p];
        if (act) {
            float2 f = __half22float2(g_h2f[(size_t)s * (NCLS / 2) + l]);
            acc.x = fmaf(f.x, wt, acc.x);
            acc.y = fmaf(f.y, wt, acc.y);
        }
    }
    if (act) {
        acc.x += b2[2 * l];
        acc.y += b2[2 * l + 1];
    }

    float m = act ? fmaxf(acc.x, acc.y) : -1e30f;
#pragma unroll
    for (int o = 16; o >= 1; o >>= 1) m = fmaxf(m, __shfl_xor_sync(0xffffffffu, m, o));
    float e = act ? (expf(acc.x - m) + expf(acc.y - m)) : 0.f;
#pragma unroll
    for (int o = 16; o >= 1; o >>= 1) e += __shfl_xor_sync(0xffffffffu, e, o);
    float lse = m + logf(e);

    if (act) {
        out[(size_t)w * NCLS + 2 * l]     = acc.x - lse;
        out[(size_t)w * NCLS + 2 * l + 1] = acc.y - lse;
    }
}

// --------------------------------- launch ----------------------------------
// gemm1 stays at launch #4 (the slot the profiler captures).
extern "C" void kernel_launch(void* const* d_in, const int* in_sizes, int n_in,
                              void* d_out, int out_size) {
    const float* x  = (const float*)d_in[0];
    const int*   ei = (const int*)d_in[1];
    const float* W1 = (const float*)d_in[2];
    const float* b1 = (const float*)d_in[3];
    const float* W2 = (const float*)d_in[4];
    const float* b2 = (const float*)d_in[5];
    float*       out = (float*)d_out;

    int N = in_sizes[0] / FIN;       // 100000
    int E = in_sizes[1] / 2;         // 1600000
    int nb = (N + 1023) / 1024;

    cudaFuncSetAttribute(k_gemm1_mma, cudaFuncAttributeMaxDynamicSharedMemorySize, G1_SMEM);

    k_wconv<<<(FIN * HID + 255) / 256, 256>>>(W1);          // 1
    k_probe<<<1, 1>>>((const unsigned*)d_in[1]);            // 2
    k_init<<<(N + 255) / 256, 256>>>(N);                    // 3
    k_gemm1_mma<<<(N + 127) / 128, 256, G1_SMEM>>>(x, N);   // 4  <- profiled
    k_wconv2<<<(HID * NCLS + 255) / 256, 256>>>(W2);        // 5
    k_hist<<<(E + 255) / 256, 256>>>(ei, E);                // 6
    k_scanA<<<nb, 1024>>>(N);                               // 7
    k_scanB<<<1, 128>>>(nb);                                // 8
    k_scanC<<<nb, 1024>>>(N);                               // 9
    k_scatter<<<(E + 255) / 256, 256>>>(ei, E);             // 10
    k_agg1<<<(N * 32 + 255) / 256, 256>>>(b1, N);           // 11
    k_gemm2_mma<<<(N + 127) / 128, 256>>>(N);               // 12
    k_agg2<<<(N * 32 + 255) / 256, 256>>>(b2, out, N);      // 13
}

// round 15
// speedup vs baseline: 1.2290x; 1.2290x over previous
#include <cuda_runtime.h>
#include <cuda_bf16.h>
#include <cuda_fp16.h>
#include <math.h>
#include <stdint.h>

// ---------------------------------------------------------------------------
// GCN 2-layer forward. R15: revert GEMM1 to R13 (2 CTA/SM > any pipelining;
// R14 falsified), unroll agg1/agg2 edge loops x4 for gather MLP.
// ---------------------------------------------------------------------------

#define NMAX 100000
#define EMAX 1600000
#define FIN  512
#define HID  128
#define NCLS 40
#define NBLK ((NMAX + 1023) / 1024)

typedef unsigned long long ull;

// --------------------------- device scratch --------------------------------
__device__ int   g_is64;
__device__ int   g_cnt[NMAX];
__device__ int   g_off[NMAX + 1];
__device__ int   g_cur[NMAX];
__device__ float g_dis[NMAX];
__device__ int   g_blksum[NBLK];
__device__ int   g_blkoff[NBLK];
__device__ int   g_esrc[EMAX];
__device__ float g_enrm[EMAX];
__device__ __align__(128) __half g_w1h[(size_t)HID * FIN];          // W1^T fp16
__device__ __align__(128) __half g_w2t[(size_t)NCLS * HID];         // W2^T fp16
__device__ __align__(128) __half2 g_h1f[(size_t)NMAX * (HID / 2)];  // x@W1
__device__ __align__(128) __half2 g_a1f[(size_t)NMAX * (HID / 2)];  // relu(agg)
__device__ __align__(128) __half2 g_h2f[(size_t)NMAX * (NCLS / 2)]; // a1@W2

// --------------------------- helpers ---------------------------------------
__device__ __forceinline__ int load_idx(const int* __restrict__ p, long long slot, int is64) {
    return is64 ? p[2 * slot] : p[slot];
}
__global__ void k_probe(const unsigned* __restrict__ p) {
    unsigned nz = 0;
    for (int i = 1; i < 256; i += 2) nz |= p[i];
    g_is64 = (nz == 0u) ? 1 : 0;
}
__device__ __forceinline__ unsigned pack_h2(float x, float y) {
    __half hx = __float2half_rn(x), hy = __float2half_rn(y);
    return (unsigned)__half_as_ushort(hx) | ((unsigned)__half_as_ushort(hy) << 16);
}
__device__ __forceinline__ float2 u32_as_f2h(unsigned u) {
    __half2 h = *reinterpret_cast<__half2*>(&u);
    return __half22float2(h);
}

#define MMA_F16(c, a, b0, b1)                                                    \
    asm volatile("mma.sync.aligned.m16n8k16.row.col.f32.f16.f16.f32 "            \
        "{%0,%1,%2,%3}, {%4,%5,%6,%7}, {%8,%9}, {%0,%1,%2,%3};"                  \
        : "+f"((c)[0]), "+f"((c)[1]), "+f"((c)[2]), "+f"((c)[3])                 \
        : "r"((a)[0]), "r"((a)[1]), "r"((a)[2]), "r"((a)[3]), "r"(b0), "r"(b1))

// --------------------------- CSR construction ------------------------------
__global__ void k_init(int n) {
    int i = blockIdx.x * blockDim.x + threadIdx.x;
    if (i < n) { g_cnt[i] = 0; g_cur[i] = 0; }
}
__global__ void k_hist(const int* __restrict__ ei, int E) {
    int e = blockIdx.x * blockDim.x + threadIdx.x;
    int is64 = g_is64;
    if (e < E) atomicAdd(&g_cnt[load_idx(ei, (long long)E + e, is64)], 1);
}
__global__ void k_scanA(int n) {
    __shared__ int sh[1024];
    int t = threadIdx.x;
    int i = blockIdx.x * 1024 + t;
    sh[t] = (i < n) ? g_cnt[i] : 0;
    __syncthreads();
#pragma unroll
    for (int d = 512; d > 0; d >>= 1) {
        if (t < d) sh[t] += sh[t + d];
        __syncthreads();
    }
    if (t == 0) g_blksum[blockIdx.x] = sh[0];
}
__global__ void k_scanB(int nb) {
    __shared__ int sh[128];
    int t = threadIdx.x;
    int v = (t < nb) ? g_blksum[t] : 0;
    sh[t] = v;
    __syncthreads();
#pragma unroll
    for (int d = 1; d < 128; d <<= 1) {
        int u = 0;
        if (t >= d) u = sh[t - d];
        __syncthreads();
        if (t >= d) sh[t] += u;
        __syncthreads();
    }
    if (t < nb) g_blkoff[t] = sh[t] - v;
}
__global__ void k_scanC(int n) {
    __shared__ int sh[1024];
    int t = threadIdx.x;
    int i = blockIdx.x * 1024 + t;
    int c = (i < n) ? g_cnt[i] : 0;
    sh[t] = c;
    __syncthreads();
#pragma unroll
    for (int d = 1; d < 1024; d <<= 1) {
        int u = 0;
        if (t >= d) u = sh[t - d];
        __syncthreads();
        if (t >= d) sh[t] += u;
        __syncthreads();
    }
    if (i < n) {
        int off = g_blkoff[blockIdx.x] + sh[t] - c;
        g_off[i] = off;
        g_dis[i] = rsqrtf((float)(c + 1));
        if (i == n - 1) g_off[n] = off + c;
    }
}
__global__ void k_scatter(const int* __restrict__ ei, int E) {
    int e = blockIdx.x * blockDim.x + threadIdx.x;
    int is64 = g_is64;
    if (e < E) {
        int s = load_idx(ei, e, is64);
        int d = load_idx(ei, (long long)E + e, is64);
        int p = g_off[d] + atomicAdd(&g_cur[d], 1);
        g_esrc[p] = s;
        g_enrm[p] = g_dis[s] * g_dis[d];
    }
}

// --------------- weight conversions (fp32 -> fp16, transposed) --------------
__global__ void k_wconv(const float* __restrict__ W1) {
    int i = blockIdx.x * blockDim.x + threadIdx.x;
    if (i < FIN * HID) {
        int k = i / HID, n = i % HID;
        g_w1h[(size_t)n * FIN + k] = __float2half_rn(W1[i]);
    }
}
__global__ void k_wconv2(const float* __restrict__ W2) {
    int i = blockIdx.x * blockDim.x + threadIdx.x;
    if (i < HID * NCLS) {
        int k = i / NCLS, n = i % NCLS;
        g_w2t[(size_t)n * HID + k] = __float2half_rn(W2[i]);
    }
}

// ---------- GEMM1 via mma.sync fp16 (R13 form): [N,512]x[512,128] ----------
#define SA 40   // smem stride in halves (conflict-free fragment reads)

__global__ __launch_bounds__(256) void k_gemm1_mma(const float* __restrict__ X, int M) {
    __shared__ __half sA[128 * SA];
    __shared__ __half sB[128 * SA];

    int t    = threadIdx.x;
    int lane = t & 31;
    int wid  = t >> 5;
    int wm   = wid & 3;
    int wn   = wid >> 2;
    int blockRow = blockIdx.x * 128;

    float acc[2][8][4];
#pragma unroll
    for (int mi = 0; mi < 2; mi++)
#pragma unroll
        for (int ni = 0; ni < 8; ni++)
#pragma unroll
            for (int c = 0; c < 4; c++) acc[mi][ni][c] = 0.f;

    const int lg = lane >> 2;
    const int lk = (lane & 3) * 2;

    for (int ch = 0; ch < 16; ch++) {
        int kt = ch * 32;
#pragma unroll
        for (int i = 0; i < 4; i++) {
            int f  = t + i * 256;
            int r  = f >> 3;
            int c4 = f & 7;
            int gr = blockRow + r;
            if (gr >= M) gr = M - 1;
            float4 v = *(const float4*)&X[(size_t)gr * FIN + kt + c4 * 4];
            ull h = (ull)pack_h2(v.x, v.y) | ((ull)pack_h2(v.z, v.w) << 32);
            *(ull*)&sA[r * SA + c4 * 4] = h;
        }
#pragma unroll
        for (int i = 0; i < 4; i++) {
            int f  = t + i * 256;
            int n  = f >> 3;
            int c4 = f & 7;
            *(ull*)&sB[n * SA + c4 * 4] = *(const ull*)&g_w1h[(size_t)n * FIN + kt + c4 * 4];
        }
        __syncthreads();

#pragma unroll
        for (int kk = 0; kk < 2; kk++) {
            int k0 = kk * 16 + lk;
            uint32_t ah[2][4];
#pragma unroll
            for (int mi = 0; mi < 2; mi++) {
                int r0 = wm * 32 + mi * 16 + lg;
                ah[mi][0] = *(const uint32_t*)&sA[r0 * SA + k0];
                ah[mi][1] = *(const uint32_t*)&sA[(r0 + 8) * SA + k0];
                ah[mi][2] = *(const uint32_t*)&sA[r0 * SA + k0 + 8];
                ah[mi][3] = *(const uint32_t*)&sA[(r0 + 8) * SA + k0 + 8];
            }
#pragma unroll
            for (int ni = 0; ni < 8; ni++) {
                int c0 = wn * 64 + ni * 8 + lg;
                uint32_t b0 = *(const uint32_t*)&sB[c0 * SA + k0];
                uint32_t b1 = *(const uint32_t*)&sB[c0 * SA + k0 + 8];
#pragma unroll
                for (int mi = 0; mi < 2; mi++)
                    MMA_F16(acc[mi][ni], ah[mi], b0, b1);
            }
        }
        __syncthreads();
    }

#pragma unroll
    for (int mi = 0; mi < 2; mi++) {
        int r0 = blockRow + wm * 32 + mi * 16 + (lane >> 2);
#pragma unroll
        for (int ni = 0; ni < 8; ni++) {
            int c2 = (wn * 64 + ni * 8 + (lane & 3) * 2) >> 1;
            if (r0 < M)
                g_h1f[(size_t)r0 * (HID / 2) + c2] = __floats2half2_rn(acc[mi][ni][0], acc[mi][ni][1]);
            if (r0 + 8 < M)
                g_h1f[(size_t)(r0 + 8) * (HID / 2) + c2] = __floats2half2_rn(acc[mi][ni][2], acc[mi][ni][3]);
        }
    }
}

// ------- Aggregation 1: warp/node, fp16 gather, x4-unrolled edge loop ------
__global__ void k_agg1(const float* __restrict__ b1, int n) {
    int w = (blockIdx.x * blockDim.x + threadIdx.x) >> 5;
    if (w >= n) return;
    int l = threadIdx.x & 31;

    float di = g_dis[w];
    float dself = di * di;

    const __half2* self = &g_h1f[(size_t)w * (HID / 2) + l * 2];
    float2 s0 = __half22float2(self[0]);
    float2 s1 = __half22float2(self[1]);
    float4 acc = make_float4(s0.x * dself, s0.y * dself, s1.x * dself, s1.y * dself);

    int beg = g_off[w], end = g_off[w + 1];
    int p = beg;
    for (; p + 4 <= end; p += 4) {
        int   s0i = g_esrc[p],     s1i = g_esrc[p + 1];
        int   s2i = g_esrc[p + 2], s3i = g_esrc[p + 3];
        float w0 = g_enrm[p],      w1 = g_enrm[p + 1];
        float w2 = g_enrm[p + 2],  w3 = g_enrm[p + 3];
        uint2 v0 = *(const uint2*)&g_h1f[(size_t)s0i * (HID / 2) + l * 2];
        uint2 v1 = *(const uint2*)&g_h1f[(size_t)s1i * (HID / 2) + l * 2];
        uint2 v2 = *(const uint2*)&g_h1f[(size_t)s2i * (HID / 2) + l * 2];
        uint2 v3 = *(const uint2*)&g_h1f[(size_t)s3i * (HID / 2) + l * 2];
        float2 a0 = u32_as_f2h(v0.x), b0v = u32_as_f2h(v0.y);
        float2 a1 = u32_as_f2h(v1.x), b1v = u32_as_f2h(v1.y);
        float2 a2 = u32_as_f2h(v2.x), b2v = u32_as_f2h(v2.y);
        float2 a3 = u32_as_f2h(v3.x), b3v = u32_as_f2h(v3.y);
        acc.x = fmaf(a0.x, w0, acc.x); acc.y = fmaf(a0.y, w0, acc.y);
        acc.z = fmaf(b0v.x, w0, acc.z); acc.w = fmaf(b0v.y, w0, acc.w);
        acc.x = fmaf(a1.x, w1, acc.x); acc.y = fmaf(a1.y, w1, acc.y);
        acc.z = fmaf(b1v.x, w1, acc.z); acc.w = fmaf(b1v.y, w1, acc.w);
        acc.x = fmaf(a2.x, w2, acc.x); acc.y = fmaf(a2.y, w2, acc.y);
        acc.z = fmaf(b2v.x, w2, acc.z); acc.w = fmaf(b2v.y, w2, acc.w);
        acc.x = fmaf(a3.x, w3, acc.x); acc.y = fmaf(a3.y, w3, acc.y);
        acc.z = fmaf(b3v.x, w3, acc.z); acc.w = fmaf(b3v.y, w3, acc.w);
    }
    for (; p < end; p++) {
        int   s  = g_esrc[p];
        float wt = g_enrm[p];
        uint2 v = *(const uint2*)&g_h1f[(size_t)s * (HID / 2) + l * 2];
        float2 f0 = u32_as_f2h(v.x);
        float2 f1 = u32_as_f2h(v.y);
        acc.x = fmaf(f0.x, wt, acc.x);
        acc.y = fmaf(f0.y, wt, acc.y);
        acc.z = fmaf(f1.x, wt, acc.z);
        acc.w = fmaf(f1.y, wt, acc.w);
    }
    float4 bb = *(const float4*)&b1[l * 4];
    acc.x = fmaxf(acc.x + bb.x, 0.f);
    acc.y = fmaxf(acc.y + bb.y, 0.f);
    acc.z = fmaxf(acc.z + bb.z, 0.f);
    acc.w = fmaxf(acc.w + bb.w, 0.f);
    uint2 o;
    o.x = pack_h2(acc.x, acc.y);
    o.y = pack_h2(acc.z, acc.w);
    *(uint2*)&g_a1f[(size_t)w * (HID / 2) + l * 2] = o;
}

// ---------- GEMM2 via mma.sync fp16: [N,128] x [128,40] -> g_h2f ----------
#define SB2 136

__global__ __launch_bounds__(256) void k_gemm2_mma(int M) {
    __shared__ __half sA[128 * SA];
    __shared__ __half sB[NCLS * SB2];

    int t    = threadIdx.x;
    int lane = t & 31;
    int wid  = t >> 5;
    int blockRow = blockIdx.x * 128;

    float acc[5][4];
#pragma unroll
    for (int ni = 0; ni < 5; ni++)
#pragma unroll
        for (int c = 0; c < 4; c++) acc[ni][c] = 0.f;

    for (int i = t; i < NCLS * (HID / 4); i += 256) {
        int n = i / (HID / 4);
        int q = i % (HID / 4);
        *(ull*)&sB[n * SB2 + q * 4] = *(const ull*)&g_w2t[(size_t)n * HID + q * 4];
    }

    const int lg = lane >> 2;
    const int lk = (lane & 3) * 2;
    const __half* a1 = (const __half*)g_a1f;

    for (int ch = 0; ch < 4; ch++) {
        int kt = ch * 32;
#pragma unroll
        for (int i = 0; i < 4; i++) {
            int f  = t + i * 256;
            int r  = f >> 3;
            int c4 = f & 7;
            int gr = blockRow + r;
            if (gr >= M) gr = M - 1;
            *(ull*)&sA[r * SA + c4 * 4] = *(const ull*)&a1[(size_t)gr * HID + kt + c4 * 4];
        }
        __syncthreads();

#pragma unroll
        for (int kk = 0; kk < 2; kk++) {
            int k0 = kk * 16 + lk;
            int r0 = wid * 16 + lg;
            uint32_t a[4];
            a[0] = *(const uint32_t*)&sA[r0 * SA + k0];
            a[1] = *(const uint32_t*)&sA[(r0 + 8) * SA + k0];
            a[2] = *(const uint32_t*)&sA[r0 * SA + k0 + 8];
            a[3] = *(const uint32_t*)&sA[(r0 + 8) * SA + k0 + 8];
            int kb = kt + kk * 16 + lk;
#pragma unroll
            for (int ni = 0; ni < 5; ni++) {
                int c0 = ni * 8 + lg;
                uint32_t b0 = *(const uint32_t*)&sB[c0 * SB2 + kb];
                uint32_t b1 = *(const uint32_t*)&sB[c0 * SB2 + kb + 8];
                MMA_F16(acc[ni], a, b0, b1);
            }
        }
        __syncthreads();
    }

    int r0 = blockRow + wid * 16 + (lane >> 2);
#pragma unroll
    for (int ni = 0; ni < 5; ni++) {
        int c2 = (ni * 8 + (lane & 3) * 2) >> 1;
        if (r0 < M)
            g_h2f[(size_t)r0 * (NCLS / 2) + c2] = __floats2half2_rn(acc[ni][0], acc[ni][1]);
        if (r0 + 8 < M)
            g_h2f[(size_t)(r0 + 8) * (NCLS / 2) + c2] = __floats2half2_rn(acc[ni][2], acc[ni][3]);
    }
}

// ------- Aggregation 2 + log_softmax: warp/node, x4-unrolled gather --------
__global__ void k_agg2(const float* __restrict__ b2, float* __restrict__ out, int n) {
    int w = (blockIdx.x * blockDim.x + threadIdx.x) >> 5;
    if (w >= n) return;
    int l = threadIdx.x & 31;
    bool act = (l < NCLS / 2);
    int lc = act ? l : 0;

    float di = g_dis[w];
    float dself = di * di;

    float2 acc = make_float2(0.f, 0.f);
    {
        float2 f = __half22float2(g_h2f[(size_t)w * (NCLS / 2) + lc]);
        acc.x = f.x * dself;
        acc.y = f.y * dself;
    }

    int beg = g_off[w], end = g_off[w + 1];
    int p = beg;
    for (; p + 4 <= end; p += 4) {
        int   s0i = g_esrc[p],     s1i = g_esrc[p + 1];
        int   s2i = g_esrc[p + 2], s3i = g_esrc[p + 3];
        float w0 = g_enrm[p],      w1 = g_enrm[p + 1];
        float w2 = g_enrm[p + 2],  w3 = g_enrm[p + 3];
        float2 f0 = __half22float2(g_h2f[(size_t)s0i * (NCLS / 2) + lc]);
        float2 f1 = __half22float2(g_h2f[(size_t)s1i * (NCLS / 2) + lc]);
        float2 f2 = __half22float2(g_h2f[(size_t)s2i * (NCLS / 2) + lc]);
        float2 f3 = __half22float2(g_h2f[(size_t)s3i * (NCLS / 2) + lc]);
        acc.x = fmaf(f0.x, w0, acc.x); acc.y = fmaf(f0.y, w0, acc.y);
        acc.x = fmaf(f1.x, w1, acc.x); acc.y = fmaf(f1.y, w1, acc.y);
        acc.x = fmaf(f2.x, w2, acc.x); acc.y = fmaf(f2.y, w2, acc.y);
        acc.x = fmaf(f3.x, w3, acc.x); acc.y = fmaf(f3.y, w3, acc.y);
    }
    for (; p < end; p++) {
        int   s  = g_esrc[p];
        float wt = g_enrm[p];
        float2 f = __half22float2(g_h2f[(size_t)s * (NCLS / 2) + lc]);
        acc.x = fmaf(f.x, wt, acc.x);
        acc.y = fmaf(f.y, wt, acc.y);
    }
    if (act) {
        acc.x += b2[2 * l];
        acc.y += b2[2 * l + 1];
    }

    float m = act ? fmaxf(acc.x, acc.y) : -1e30f;
#pragma unroll
    for (int o = 16; o >= 1; o >>= 1) m = fmaxf(m, __shfl_xor_sync(0xffffffffu, m, o));
    float e = act ? (expf(acc.x - m) + expf(acc.y - m)) : 0.f;
#pragma unroll
    for (int o = 16; o >= 1; o >>= 1) e += __shfl_xor_sync(0xffffffffu, e, o);
    float lse = m + logf(e);

    if (act) {
        out[(size_t)w * NCLS + 2 * l]     = acc.x - lse;
        out[(size_t)w * NCLS + 2 * l + 1] = acc.y - lse;
    }
}

// --------------------------------- launch ----------------------------------
// gemm1 stays at launch #4 (the slot the profiler captures).
extern "C" void kernel_launch(void* const* d_in, const int* in_sizes, int n_in,
                              void* d_out, int out_size) {
    const float* x  = (const float*)d_in[0];
    const int*   ei = (const int*)d_in[1];
    const float* W1 = (const float*)d_in[2];
    const float* b1 = (const float*)d_in[3];
    const float* W2 = (const float*)d_in[4];
    const float* b2 = (const float*)d_in[5];
    float*       out = (float*)d_out;

    int N = in_sizes[0] / FIN;       // 100000
    int E = in_sizes[1] / 2;         // 1600000
    int nb = (N + 1023) / 1024;

    k_wconv<<<(FIN * HID + 255) / 256, 256>>>(W1);          // 1
    k_probe<<<1, 1>>>((const unsigned*)d_in[1]);            // 2
    k_init<<<(N + 255) / 256, 256>>>(N);                    // 3
    k_gemm1_mma<<<(N + 127) / 128, 256>>>(x, N);            // 4  <- profiled
    k_wconv2<<<(HID * NCLS + 255) / 256, 256>>>(W2);        // 5
    k_hist<<<(E + 255) / 256, 256>>>(ei, E);                // 6
    k_scanA<<<nb, 1024>>>(N);                               // 7
    k_scanB<<<1, 128>>>(nb);                                // 8
    k_scanC<<<nb, 1024>>>(N);                               // 9
    k_scatter<<<(E + 255) / 256, 256>>>(ei, E);             // 10
    k_agg1<<<(N * 32 + 255) / 256, 256>>>(b1, N);           // 11
    k_gemm2_mma<<<(N + 127) / 128, 256>>>(N);               // 12
    k_agg2<<<(N * 32 + 255) / 256, 256>>>(b2, out, N);      // 13
}